// round 15
// baseline (speedup 1.0000x reference)
#include <cuda_runtime.h>
#include <math.h>

#define G 8192
#define S 64
#define D 128
#define H 256
#define EPS 0.01f

// Output layout: rep [G*D] | mixture [G*8] | scale [G] | alpha [G] | beta [G]
#define O_REP   0
#define O_MIX   (G * D)
#define O_SCALE (O_MIX + G * 8)
#define O_ALPHA (O_SCALE + G)
#define O_BETA  (O_ALPHA + G)

#define CGROUPS 16               // groups per MLP block
#define NCONS (G / CGROUPS)      // 512 MLP blocks
#define ATPAD (CGROUPS + 2)      // padded row stride (keeps 8B alignment, spreads banks)

typedef unsigned long long ull;

__device__ __forceinline__ ull pack2(float lo, float hi) {
    ull r;
    asm("mov.b64 %0, {%1, %2};" : "=l"(r) : "f"(lo), "f"(hi));
    return r;
}
__device__ __forceinline__ void unpack2(ull v, float& lo, float& hi) {
    asm("mov.b64 {%0, %1}, %2;" : "=f"(lo), "=f"(hi) : "l"(v));
}
__device__ __forceinline__ void fma2(ull& d, ull a, ull b) {
    asm("fma.rn.f32x2 %0, %1, %2, %0;" : "+l"(d) : "l"(a), "l"(b));
}

// tanh via exp: rel err ~1e-6 (MUFU.EX2 + fast rcp), ~6 instrs, no libm bloat.
__device__ __forceinline__ float fast_tanh(float x) {
    float e = __expf(2.f * x);
    return 1.f - __fdividef(2.f, e + 1.f);
}
// softplus with fast exp/log; large-|v| asymptotics exact.
__device__ __forceinline__ float softplus_f(float v) {
    return fmaxf(v, 0.f) + __logf(1.f + __expf(-fabsf(v)));
}

// ---------------------------------------------------------------------------
// Kernel 1: per-group statistics -> rep. EXACT R3 body (proven, do not touch).
// ---------------------------------------------------------------------------
__global__ __launch_bounds__(256) void stats_kernel(
    const float* __restrict__ x, const float* __restrict__ y,
    const float* __restrict__ ax, const float* __restrict__ ay,
    float* __restrict__ rep)
{
    const int warp = threadIdx.x >> 5;
    const int lane = threadIdx.x & 31;
    const int g = blockIdx.x * 8 + warp;

    const float4* xg = reinterpret_cast<const float4*>(x + (size_t)g * S * D) + lane;
    const float4  a4 = reinterpret_cast<const float4*>(ax + (size_t)g * D)[lane];
    const float   ayv = ay[g];
    const float*  yg = y + (size_t)g * S;

    float sx0 = 0.f, sx1 = 0.f, sx2 = 0.f, sx3 = 0.f;
    float sp0 = 0.f, sp1 = 0.f, sp2 = 0.f, sp3 = 0.f;
    float sxx = 0.f, sy = 0.f;

#pragma unroll 4
    for (int s = 0; s < S; ++s) {
        float4 xv = xg[s * 32];
        float  yv = __ldg(yg + s);
        float xr0 = xv.x - a4.x;
        float xr1 = xv.y - a4.y;
        float xr2 = xv.z - a4.z;
        float xr3 = xv.w - a4.w;
        float yr  = yv - ayv;
        sx0 += xr0; sx1 += xr1; sx2 += xr2; sx3 += xr3;
        sp0 += xr0 * yr; sp1 += xr1 * yr; sp2 += xr2 * yr; sp3 += xr3 * yr;
        sxx += xr0 * xr0 + xr1 * xr1 + xr2 * xr2 + xr3 * xr3;
        sy  += yr;
    }

    float tot = sx0 + sx1 + sx2 + sx3;
    float sxxT = sxx;
#pragma unroll
    for (int o = 16; o > 0; o >>= 1) {
        tot  += __shfl_xor_sync(0xffffffffu, tot,  o);
        sxxT += __shfl_xor_sync(0xffffffffu, sxxT, o);
    }

    const float nD = (float)(S * D);
    const float var = (sxxT - tot * tot / nD) / (nD - 1.f);
    const float inv = 1.f / var;
    const float invn  = 1.f / (float)S;
    const float invn1 = 1.f / (float)(S - 1);

    float4 r;
    r.x = (sp0 - sx0 * sy * invn) * invn1 * inv;
    r.y = (sp1 - sx1 * sy * invn) * invn1 * inv;
    r.z = (sp2 - sx2 * sy * invn) * invn1 * inv;
    r.w = (sp3 - sx3 * sy * invn) * invn1 * inv;
    reinterpret_cast<float4*>(rep + (size_t)g * D)[lane] = r;
}

// ---------------------------------------------------------------------------
// Kernel 2: MLP head. 512 blocks x 256 threads, forced <=64 regs (4 CTAs/SM).
// A transposed in smem (sAT[k][row]) -> per-k: 2x LDS.64 broadcast of a row
// pair feeding row-paired f32x2 FMAs. W1 direct from gmem (L1-resident).
// Thread = rows [4*rg, 4*rg+4) x cols [c0, c0+4).
// ---------------------------------------------------------------------------
__global__ __launch_bounds__(256, 4) void mlp_kernel(
    const float* __restrict__ rep, const float* __restrict__ W1,
    const float* __restrict__ b1, const float* __restrict__ W2,
    const float* __restrict__ b2, float* __restrict__ out)
{
    __shared__ __align__(16) float sAT[D][ATPAD];  // 9 KB transposed A
    __shared__ float sH[CGROUPS * H];              // 16 KB
    __shared__ float sW2[H * 10];                  // 10 KB

    const int t = threadIdx.x;
    const int m = blockIdx.x;           // groups [16m, 16m+16)
    const int warp = t >> 5;
    const int lane = t & 31;

    for (int i = t; i < H * 10; i += 256) sW2[i] = W2[i];

    // load + transpose A tile: element (row, k); coalesced in k
    {
        const float* src = rep + (size_t)m * CGROUPS * D;
#pragma unroll
        for (int i = 0; i < 8; ++i) {
            int idx = t + i * 256;          // 0..2047
            int k = idx & 127;
            int row = idx >> 7;
            sAT[k][row] = src[row * D + k];
        }
    }
    __syncthreads();

    // ---- GEMM1 + tanh ----
    {
        const int rg = t >> 6;            // 0..3 -> rows [4rg, 4rg+4)
        const int c0 = (t & 63) * 4;      // cols [c0, c0+4)
        const float4* W1v = reinterpret_cast<const float4*>(W1) + (c0 >> 2);

        ull acc[2][4];                    // [row pair][col]; f32x2 lanes = rows
#pragma unroll
        for (int p = 0; p < 2; ++p)
#pragma unroll
            for (int c = 0; c < 4; ++c) acc[p][c] = pack2(0.f, 0.f);

#pragma unroll 4
        for (int k = 0; k < D; ++k) {
            float4 w = W1v[k * (H / 4)];
            ull a0 = *reinterpret_cast<const ull*>(&sAT[k][4 * rg]);      // rows 4rg,4rg+1
            ull a1 = *reinterpret_cast<const ull*>(&sAT[k][4 * rg + 2]);  // rows 4rg+2,4rg+3
            ull wx = pack2(w.x, w.x);
            ull wy = pack2(w.y, w.y);
            ull wz = pack2(w.z, w.z);
            ull ww = pack2(w.w, w.w);
            fma2(acc[0][0], a0, wx); fma2(acc[1][0], a1, wx);
            fma2(acc[0][1], a0, wy); fma2(acc[1][1], a1, wy);
            fma2(acc[0][2], a0, wz); fma2(acc[1][2], a1, wz);
            fma2(acc[0][3], a0, ww); fma2(acc[1][3], a1, ww);
        }

        float4 bb = reinterpret_cast<const float4*>(b1)[c0 >> 2];
        const float bbv[4] = {bb.x, bb.y, bb.z, bb.w};
#pragma unroll
        for (int p = 0; p < 2; ++p) {
            float4 hlo, hhi;
            float* lo = &hlo.x;
            float* hi = &hhi.x;
#pragma unroll
            for (int c = 0; c < 4; ++c) {
                float v0, v1;
                unpack2(acc[p][c], v0, v1);
                lo[c] = fast_tanh(v0 + bbv[c]);
                hi[c] = fast_tanh(v1 + bbv[c]);
            }
            *reinterpret_cast<float4*>(sH + (4 * rg + 2 * p) * H + c0)     = hlo;
            *reinterpret_cast<float4*>(sH + (4 * rg + 2 * p + 1) * H + c0) = hhi;
        }
    }
    __syncthreads();

    // ---- GEMM2 + epilogue: warp handles groups {2*warp, 2*warp+1} ----
#pragma unroll
    for (int i = 0; i < 2; ++i) {
        const int row = warp * 2 + i;
        const float* hrow = sH + row * H;

        float p[10];
#pragma unroll
        for (int k = 0; k < 10; ++k) p[k] = 0.f;

#pragma unroll
        for (int j = 0; j < 8; ++j) {
            float hv = hrow[lane + 32 * j];
            const float* w2r = sW2 + (lane + 32 * j) * 10;
#pragma unroll
            for (int k = 0; k < 10; ++k) p[k] += hv * w2r[k];
        }
#pragma unroll
        for (int k = 0; k < 10; ++k) {
#pragma unroll
            for (int o = 16; o > 0; o >>= 1)
                p[k] += __shfl_xor_sync(0xffffffffu, p[k], o);
        }

        if (lane == 0) {
            const int g = m * CGROUPS + row;
            float o0 = p[0] + __ldg(b2 + 0);
            float o1 = p[1] + __ldg(b2 + 1);
            float alpha = softplus_f(o0) * (1.f - EPS) + EPS;
            float beta  = softplus_f(o1) * (1.f - EPS) + EPS;

            float lg[8];
            float mx = -3.4e38f;
#pragma unroll
            for (int k = 0; k < 8; ++k) {
                lg[k] = p[2 + k] + __ldg(b2 + 2 + k);
                mx = fmaxf(mx, lg[k]);
            }
            float se = 0.f;
#pragma unroll
            for (int k = 0; k < 8; ++k) { lg[k] = __expf(lg[k] - mx); se += lg[k]; }
            float inv_se = __fdividef(1.f, se);
#pragma unroll
            for (int k = 0; k < 8; ++k) out[O_MIX + (size_t)g * 8 + k] = lg[k] * inv_se;

            out[O_SCALE + g] = sqrtf(__fdividef(beta, alpha));
            out[O_ALPHA + g] = alpha;
            out[O_BETA  + g] = beta;
        }
    }
}

// ---------------------------------------------------------------------------
extern "C" void kernel_launch(void* const* d_in, const int* in_sizes, int n_in,
                              void* d_out, int out_size)
{
    (void)in_sizes; (void)n_in; (void)out_size;
    // inputs: 0=index(int32), 1=x, 2=y, 3=anchor_x, 4=anchor_y, 5=W1, 6=b1, 7=W2, 8=b2
    const float* x  = (const float*)d_in[1];
    const float* y  = (const float*)d_in[2];
    const float* ax = (const float*)d_in[3];
    const float* ay = (const float*)d_in[4];
    const float* W1 = (const float*)d_in[5];
    const float* b1 = (const float*)d_in[6];
    const float* W2 = (const float*)d_in[7];
    const float* b2 = (const float*)d_in[8];
    float* out = (float*)d_out;

    stats_kernel<<<G / 8, 256>>>(x, y, ax, ay, out + O_REP);
    mlp_kernel<<<NCONS, 256>>>(out + O_REP, W1, b1, W2, b2, out);
}

// round 17
// speedup vs baseline: 1.0710x; 1.0710x over previous
#include <cuda_runtime.h>
#include <math.h>

#define G 8192
#define S 64
#define D 128
#define H 256
#define EPS 0.01f

// Output layout: rep [G*D] | mixture [G*8] | scale [G] | alpha [G] | beta [G]
#define O_REP   0
#define O_MIX   (G * D)
#define O_SCALE (O_MIX + G * 8)
#define O_ALPHA (O_SCALE + G)
#define O_BETA  (O_ALPHA + G)

#define ROWS 32                  // groups per MLP block
#define KC   32                  // k-chunk depth
#define NCHUNK (D / KC)          // 4
#define ATPAD (ROWS + 2)         // even -> 8B alignment for LDS.64 pairs

typedef unsigned long long ull;

__device__ __forceinline__ ull pack2(float lo, float hi) {
    ull r;
    asm("mov.b64 %0, {%1, %2};" : "=l"(r) : "f"(lo), "f"(hi));
    return r;
}
__device__ __forceinline__ void unpack2(ull v, float& lo, float& hi) {
    asm("mov.b64 {%0, %1}, %2;" : "=f"(lo), "=f"(hi) : "l"(v));
}
__device__ __forceinline__ void fma2(ull& d, ull a, ull b) {
    asm("fma.rn.f32x2 %0, %1, %2, %0;" : "+l"(d) : "l"(a), "l"(b));
}

// tanh via exp: rel err ~1e-6, few instrs (validated R15: rel_err unchanged)
__device__ __forceinline__ float fast_tanh(float x) {
    float e = __expf(2.f * x);
    return 1.f - __fdividef(2.f, e + 1.f);
}
__device__ __forceinline__ float softplus_f(float v) {
    return fmaxf(v, 0.f) + __logf(1.f + __expf(-fabsf(v)));
}

// ---------------------------------------------------------------------------
// Kernel 1: per-group statistics -> rep. EXACT R3 body (proven, do not touch).
// ---------------------------------------------------------------------------
__global__ __launch_bounds__(256) void stats_kernel(
    const float* __restrict__ x, const float* __restrict__ y,
    const float* __restrict__ ax, const float* __restrict__ ay,
    float* __restrict__ rep)
{
    const int warp = threadIdx.x >> 5;
    const int lane = threadIdx.x & 31;
    const int g = blockIdx.x * 8 + warp;

    const float4* xg = reinterpret_cast<const float4*>(x + (size_t)g * S * D) + lane;
    const float4  a4 = reinterpret_cast<const float4*>(ax + (size_t)g * D)[lane];
    const float   ayv = ay[g];
    const float*  yg = y + (size_t)g * S;

    float sx0 = 0.f, sx1 = 0.f, sx2 = 0.f, sx3 = 0.f;
    float sp0 = 0.f, sp1 = 0.f, sp2 = 0.f, sp3 = 0.f;
    float sxx = 0.f, sy = 0.f;

#pragma unroll 4
    for (int s = 0; s < S; ++s) {
        float4 xv = xg[s * 32];
        float  yv = __ldg(yg + s);
        float xr0 = xv.x - a4.x;
        float xr1 = xv.y - a4.y;
        float xr2 = xv.z - a4.z;
        float xr3 = xv.w - a4.w;
        float yr  = yv - ayv;
        sx0 += xr0; sx1 += xr1; sx2 += xr2; sx3 += xr3;
        sp0 += xr0 * yr; sp1 += xr1 * yr; sp2 += xr2 * yr; sp3 += xr3 * yr;
        sxx += xr0 * xr0 + xr1 * xr1 + xr2 * xr2 + xr3 * xr3;
        sy  += yr;
    }

    float tot = sx0 + sx1 + sx2 + sx3;
    float sxxT = sxx;
#pragma unroll
    for (int o = 16; o > 0; o >>= 1) {
        tot  += __shfl_xor_sync(0xffffffffu, tot,  o);
        sxxT += __shfl_xor_sync(0xffffffffu, sxxT, o);
    }

    const float nD = (float)(S * D);
    const float var = (sxxT - tot * tot / nD) / (nD - 1.f);
    const float inv = 1.f / var;
    const float invn  = 1.f / (float)S;
    const float invn1 = 1.f / (float)(S - 1);

    float4 r;
    r.x = (sp0 - sx0 * sy * invn) * invn1 * inv;
    r.y = (sp1 - sx1 * sy * invn) * invn1 * inv;
    r.z = (sp2 - sx2 * sy * invn) * invn1 * inv;
    r.w = (sp3 - sx3 * sy * invn) * invn1 * inv;
    reinterpret_cast<float4*>(rep + (size_t)g * D)[lane] = r;
}

// ---------------------------------------------------------------------------
// Kernel 2: MLP head. 256 blocks x 256 threads, 3 CTAs/SM target.
// R5 skeleton: W1 in KC=32 smem chunks (2 syncs/chunk). A transposed in smem
// (LDS.64 broadcast of row pairs). f32x2 FMA, fast transcendentals.
// Thread = rows [8*rg, 8*rg+8) x cols [c0, c0+4);  rg = t>>6, c0 = (t&63)*4.
// sH aliased into dead sW buffer after the mainloop.
// ---------------------------------------------------------------------------
__global__ __launch_bounds__(256, 3) void mlp_kernel(
    const float* __restrict__ rep, const float* __restrict__ W1,
    const float* __restrict__ b1, const float* __restrict__ W2,
    const float* __restrict__ b2, float* __restrict__ out)
{
    __shared__ __align__(16) float sAT[D][ATPAD];  // 17 KB transposed A
    __shared__ __align__(16) float sW[KC * H];     // 32 KB (also sH after loop)
    __shared__ float sW2[H * 10];                  // 10 KB

    const int t = threadIdx.x;
    const int m = blockIdx.x;            // groups [32m, 32m+32)
    const int warp = t >> 5;
    const int lane = t & 31;
    const int rg = t >> 6;               // 0..3
    const int c0 = (t & 63) * 4;

    for (int i = t; i < H * 10; i += 256) sW2[i] = W2[i];

    // load + transpose A tile (32 rows x 128), coalesced reads
    {
        const float* src = rep + (size_t)m * ROWS * D;
#pragma unroll
        for (int i = 0; i < 16; ++i) {
            int idx = t + i * 256;       // 0..4095
            int k = idx & 127;
            int row = idx >> 7;
            sAT[k][row] = src[row * D + k];
        }
    }

    ull acc[4][4];                       // [row pair][col], f32x2 lanes = rows
#pragma unroll
    for (int p = 0; p < 4; ++p)
#pragma unroll
        for (int c = 0; c < 4; ++c) acc[p][c] = pack2(0.f, 0.f);

#pragma unroll 1
    for (int c = 0; c < NCHUNK; ++c) {
        // cooperative load of W1 chunk [KC x H] = 2048 float4
        __syncthreads();
        {
            const float4* src = reinterpret_cast<const float4*>(W1 + c * KC * H);
            float4* dst = reinterpret_cast<float4*>(sW);
#pragma unroll
            for (int i = 0; i < 8; ++i) dst[t + i * 256] = src[t + i * 256];
        }
        __syncthreads();

#pragma unroll 4
        for (int kk = 0; kk < KC; ++kk) {
            const int k = c * KC + kk;
            float4 w = *reinterpret_cast<const float4*>(sW + kk * H + c0);
            ull a0 = *reinterpret_cast<const ull*>(&sAT[k][8 * rg]);
            ull a1 = *reinterpret_cast<const ull*>(&sAT[k][8 * rg + 2]);
            ull a2 = *reinterpret_cast<const ull*>(&sAT[k][8 * rg + 4]);
            ull a3 = *reinterpret_cast<const ull*>(&sAT[k][8 * rg + 6]);
            ull wx = pack2(w.x, w.x);
            ull wy = pack2(w.y, w.y);
            ull wz = pack2(w.z, w.z);
            ull ww = pack2(w.w, w.w);
            fma2(acc[0][0], a0, wx); fma2(acc[0][1], a0, wy);
            fma2(acc[0][2], a0, wz); fma2(acc[0][3], a0, ww);
            fma2(acc[1][0], a1, wx); fma2(acc[1][1], a1, wy);
            fma2(acc[1][2], a1, wz); fma2(acc[1][3], a1, ww);
            fma2(acc[2][0], a2, wx); fma2(acc[2][1], a2, wy);
            fma2(acc[2][2], a2, wz); fma2(acc[2][3], a2, ww);
            fma2(acc[3][0], a3, wx); fma2(acc[3][1], a3, wy);
            fma2(acc[3][2], a3, wz); fma2(acc[3][3], a3, ww);
        }
    }
    __syncthreads();                     // all reads of sW done

    // tanh -> sH (alias of sW, 32*256 floats exactly)
    float* sH = sW;
    {
        float4 bb = reinterpret_cast<const float4*>(b1)[c0 >> 2];
        const float bbv[4] = {bb.x, bb.y, bb.z, bb.w};
#pragma unroll
        for (int p = 0; p < 4; ++p) {
            float4 hlo, hhi;
            float* lo = &hlo.x;
            float* hi = &hhi.x;
#pragma unroll
            for (int c = 0; c < 4; ++c) {
                float v0, v1;
                unpack2(acc[p][c], v0, v1);
                lo[c] = fast_tanh(v0 + bbv[c]);
                hi[c] = fast_tanh(v1 + bbv[c]);
            }
            *reinterpret_cast<float4*>(sH + (8 * rg + 2 * p) * H + c0)     = hlo;
            *reinterpret_cast<float4*>(sH + (8 * rg + 2 * p + 1) * H + c0) = hhi;
        }
    }
    __syncthreads();

    // ---- GEMM2 + epilogue: warp handles rows [4*warp, 4*warp+4) ----
#pragma unroll
    for (int i = 0; i < 4; ++i) {
        const int row = warp * 4 + i;
        const float* hrow = sH + row * H;

        float p[10];
#pragma unroll
        for (int k = 0; k < 10; ++k) p[k] = 0.f;

#pragma unroll
        for (int j = 0; j < 8; ++j) {
            float hv = hrow[lane + 32 * j];
            const float* w2r = sW2 + (lane + 32 * j) * 10;
#pragma unroll
            for (int k = 0; k < 10; ++k) p[k] += hv * w2r[k];
        }
#pragma unroll
        for (int k = 0; k < 10; ++k) {
#pragma unroll
            for (int o = 16; o > 0; o >>= 1)
                p[k] += __shfl_xor_sync(0xffffffffu, p[k], o);
        }

        if (lane == 0) {
            const int g = m * ROWS + row;
            float o0 = p[0] + __ldg(b2 + 0);
            float o1 = p[1] + __ldg(b2 + 1);
            float alpha = softplus_f(o0) * (1.f - EPS) + EPS;
            float beta  = softplus_f(o1) * (1.f - EPS) + EPS;

            float lg[8];
            float mx = -3.4e38f;
#pragma unroll
            for (int k = 0; k < 8; ++k) {
                lg[k] = p[2 + k] + __ldg(b2 + 2 + k);
                mx = fmaxf(mx, lg[k]);
            }
            float se = 0.f;
#pragma unroll
            for (int k = 0; k < 8; ++k) { lg[k] = __expf(lg[k] - mx); se += lg[k]; }
            float inv_se = __fdividef(1.f, se);
#pragma unroll
            for (int k = 0; k < 8; ++k) out[O_MIX + (size_t)g * 8 + k] = lg[k] * inv_se;

            out[O_SCALE + g] = sqrtf(__fdividef(beta, alpha));
            out[O_ALPHA + g] = alpha;
            out[O_BETA  + g] = beta;
        }
    }
}

// ---------------------------------------------------------------------------
extern "C" void kernel_launch(void* const* d_in, const int* in_sizes, int n_in,
                              void* d_out, int out_size)
{
    (void)in_sizes; (void)n_in; (void)out_size;
    // inputs: 0=index(int32), 1=x, 2=y, 3=anchor_x, 4=anchor_y, 5=W1, 6=b1, 7=W2, 8=b2
    const float* x  = (const float*)d_in[1];
    const float* y  = (const float*)d_in[2];
    const float* ax = (const float*)d_in[3];
    const float* ay = (const float*)d_in[4];
    const float* W1 = (const float*)d_in[5];
    const float* b1 = (const float*)d_in[6];
    const float* W2 = (const float*)d_in[7];
    const float* b2 = (const float*)d_in[8];
    float* out = (float*)d_out;

    stats_kernel<<<G / 8, 256>>>(x, y, ax, ay, out + O_REP);
    mlp_kernel<<<G / ROWS, 256>>>(out + O_REP, W1, b1, W2, b2, out);
}